// round 15
// baseline (speedup 1.0000x reference)
#include <cuda_runtime.h>
#include <cuda_fp16.h>
#include <cstdint>

// ====================== problem constants ======================
#define M_TOTAL 8192
#define N_TOTAL 16384
#define K_TOTAL 4096

#define TM 128
#define TN 256
#define TKS 128                  // fp16 elems of K per pipeline stage (2 x 64 sub-tiles)
#define STAGES 2
#define SITERS (K_TOTAL / TKS)   // 32 stage-iterations per tile
#define NTILES ((M_TOTAL / TM) * (N_TOTAL / TN))   // 4096
#define THREADS 288              // 8 consumer warps (2Mx4N of 64x64) + 1 producer warp

// sub-tile sizes (64-k granularity, matching the pre-tiled layout)
#define A_SUB   (TM * 64 * 2)            // 16384
#define W_SUB   (TN * 64 * 2)            // 32768
#define A_STG   (2 * A_SUB)              // 32768
#define W_STG   (2 * W_SUB)              // 65536
#define STAGE_BYTES (A_STG + W_STG)      // 98304

#define OFF_BAR   (STAGES * STAGE_BYTES)   // 196608: [full(8B), empty(8B)] x STAGES
#define SMEM_NEED (OFF_BAR + STAGES * 16)
#define SMEM_DYN  (SMEM_NEED + 1024)

// ====================== device scratch (pre-swizzled tiled layouts) ==================
// A: sub-tiles [mt][k64], 128 rows x 128B (SW128-swizzled), 16KB each, contiguous along k64
// W: sub-tiles [nt][k64], 256 rows x 128B (SW128-swizzled), 32KB each, contiguous along k64
__device__ __align__(128) __half g_A[(size_t)M_TOTAL * K_TOTAL];
__device__ __align__(128) __half g_W[(size_t)N_TOTAL * K_TOTAL];

// ====================== PTX helpers (generic PTX only) ======================
__device__ __forceinline__ uint32_t smem_u32(const void* p) {
    uint32_t a;
    asm("{ .reg .u64 t; cvta.to.shared.u64 t, %1; cvt.u32.u64 %0, t; }" : "=r"(a) : "l"(p));
    return a;
}

#define MBAR_INIT(addr, cnt) \
    asm volatile("mbarrier.init.shared.b64 [%0], %1;" :: "r"(addr), "r"(cnt) : "memory")

#define MBAR_EXPECT_TX(addr, bytes) \
    asm volatile("mbarrier.arrive.expect_tx.shared.b64 _, [%0], %1;" :: "r"(addr), "r"(bytes) : "memory")

#define MBAR_ARRIVE(addr) \
    asm volatile("mbarrier.arrive.shared.b64 _, [%0];" :: "r"(addr) : "memory")

__device__ __forceinline__ void mbar_wait(uint32_t mbar, uint32_t parity) {
    asm volatile(
        "{\n\t.reg .pred P;\n\t"
        "WAIT_%=:\n\t"
        "mbarrier.try_wait.parity.acquire.cta.shared::cta.b64 P, [%0], %1, 0x989680;\n\t"
        "@P bra.uni DONE_%=;\n\t"
        "bra.uni WAIT_%=;\n\t"
        "DONE_%=:\n\t}"
        :: "r"(mbar), "r"(parity) : "memory");
}

__device__ __forceinline__ void mbar_wait_relaxed(uint32_t mbar, uint32_t parity) {
    asm volatile(
        "{\n\t.reg .pred P;\n\t"
        "WAIT_%=:\n\t"
        "mbarrier.try_wait.parity.relaxed.cta.shared::cta.b64 P, [%0], %1, 0x989680;\n\t"
        "@P bra.uni DONE_%=;\n\t"
        "bra.uni WAIT_%=;\n\t"
        "DONE_%=:\n\t}"
        :: "r"(mbar), "r"(parity) : "memory");
}

__device__ __forceinline__ void bulk_g2s(uint32_t dst, const void* src, uint32_t bytes, uint32_t mbar) {
    asm volatile(
        "cp.async.bulk.shared::cluster.global.mbarrier::complete_tx::bytes [%0], [%1], %2, [%3];"
        :: "r"(dst), "l"(src), "r"(bytes), "r"(mbar) : "memory");
}

__device__ __forceinline__ void ldsm4(uint32_t* r, uint32_t addr) {
    asm volatile("ldmatrix.sync.aligned.m8n8.x4.shared.b16 {%0,%1,%2,%3}, [%4];"
                 : "=r"(r[0]), "=r"(r[1]), "=r"(r[2]), "=r"(r[3]) : "r"(addr));
}

__device__ __forceinline__ void mma16816(float* c, const uint32_t* a, uint32_t b0, uint32_t b1) {
    asm volatile(
        "mma.sync.aligned.m16n8k16.row.col.f32.f16.f16.f32 "
        "{%0,%1,%2,%3}, {%4,%5,%6,%7}, {%8,%9}, {%0,%1,%2,%3};"
        : "+f"(c[0]), "+f"(c[1]), "+f"(c[2]), "+f"(c[3])
        : "r"(a[0]), "r"(a[1]), "r"(a[2]), "r"(a[3]), "r"(b0), "r"(b1));
}

// evict-first fp32x2 store: keep 512MB output stream from thrashing W tiles in L2
__device__ __forceinline__ void st_cs_f32x2(float* p, float x, float y) {
    asm volatile("st.global.cs.v2.f32 [%0], {%1, %2};" :: "l"(p), "f"(x), "f"(y) : "memory");
}

// streaming 16B load / store for the conv pass (data touched exactly once)
__device__ __forceinline__ uint4 ld_cs_u4(const void* p) {
    uint4 v;
    asm volatile("ld.global.cs.v4.u32 {%0,%1,%2,%3}, [%4];"
                 : "=r"(v.x), "=r"(v.y), "=r"(v.z), "=r"(v.w) : "l"(p));
    return v;
}
__device__ __forceinline__ void st_cs_u4(void* p, uint4 v) {
    asm volatile("st.global.cs.v4.u32 [%0], {%1,%2,%3,%4};"
                 :: "l"(p), "r"(v.x), "r"(v.y), "r"(v.z), "r"(v.w) : "memory");
}

// ====================== merged pre-convert kernel (swizzled tiled layout) ======
#define A_CHUNKS ((M_TOTAL * K_TOTAL) / 8)   // 4194304
#define W_CHUNKS ((N_TOTAL * K_TOTAL) / 8)   // 8388608
#define ALL_CHUNKS (A_CHUNKS + W_CHUNKS)     // 12582912

__global__ void conv_both(const float4* __restrict__ inA, const int4* __restrict__ inW,
                          char* __restrict__ outA, char* __restrict__ outW) {
    int t = blockIdx.x * blockDim.x + threadIdx.x;
    if (t < A_CHUNKS) {
        int c  = t & 7;
        int r  = (t >> 3) & 127;
        int it = (t >> 10) & 63;
        int mt = t >> 16;
        int m = mt * 128 + r;
        int k = it * 64 + c * 8;
        const float4* src = inA + ((size_t)m * K_TOTAL + k) / 4;
        uint4 u0 = ld_cs_u4(src);
        uint4 u1 = ld_cs_u4(src + 1);
        float4 v0 = *reinterpret_cast<float4*>(&u0);
        float4 v1 = *reinterpret_cast<float4*>(&u1);
        __half2 h0 = __floats2half2_rn(v0.x, v0.y);
        __half2 h1 = __floats2half2_rn(v0.z, v0.w);
        __half2 h2 = __floats2half2_rn(v1.x, v1.y);
        __half2 h3 = __floats2half2_rn(v1.z, v1.w);
        size_t off = (size_t)(mt * 64 + it) * A_SUB + r * 128 + ((c * 16) ^ ((r & 7) << 4));
        uint4 pk;
        pk.x = *(uint32_t*)&h0; pk.y = *(uint32_t*)&h1;
        pk.z = *(uint32_t*)&h2; pk.w = *(uint32_t*)&h3;
        st_cs_u4(outA + off, pk);
    } else {
        t -= A_CHUNKS;
        if (t >= W_CHUNKS) return;
        int c  = t & 7;
        int r  = (t >> 3) & 255;
        int it = (t >> 11) & 63;
        int nt = t >> 17;
        int n = nt * 256 + r;
        int k = it * 64 + c * 8;
        const int4* src = inW + ((size_t)n * K_TOTAL + k) / 4;
        uint4 u0 = ld_cs_u4(src);
        uint4 u1 = ld_cs_u4(src + 1);
        int4 w0 = *reinterpret_cast<int4*>(&u0);
        int4 w1 = *reinterpret_cast<int4*>(&u1);
        __half2 h0 = __floats2half2_rn((float)w0.x, (float)w0.y);  // exact: |w|<=127
        __half2 h1 = __floats2half2_rn((float)w0.z, (float)w0.w);
        __half2 h2 = __floats2half2_rn((float)w1.x, (float)w1.y);
        __half2 h3 = __floats2half2_rn((float)w1.z, (float)w1.w);
        size_t off = (size_t)(nt * 64 + it) * W_SUB + r * 128 + ((c * 16) ^ ((r & 7) << 4));
        uint4 pk;
        pk.x = *(uint32_t*)&h0; pk.y = *(uint32_t*)&h1;
        pk.z = *(uint32_t*)&h2; pk.w = *(uint32_t*)&h3;
        st_cs_u4(outW + off, pk);
    }
}

// ====================== tile mapping ============
__device__ __forceinline__ void tile_mn(int t, int& m0, int& n0) {
    const int G = 8;
    const int MT = M_TOTAL / TM;          // 64
    const int PER = G * MT;               // 512
    int grp = t / PER;
    int r = t % PER;
    int nt = grp * G + (r % G);
    int mt = r / G;
    m0 = mt * TM;
    n0 = nt * TN;
}

// ====================== persistent warp-specialized GEMM (8 x 64x64 warps) =====
__global__ void __launch_bounds__(THREADS, 1) qlinear_gemm(
    const float* __restrict__ scale,
    const float* __restrict__ bias,
    float* __restrict__ out)
{
    extern __shared__ char smem_raw[];
    uint32_t raw = smem_u32(smem_raw);
    uint32_t pad = (1024u - (raw & 1023u)) & 1023u;
    uint32_t sb = raw + pad;

    const int tid = threadIdx.x;
    const int wid = tid >> 5;
    const int lid = tid & 31;

    if (tid == 0) {
        #pragma unroll
        for (int s = 0; s < STAGES; ++s) {
            MBAR_INIT(sb + OFF_BAR + s * 16, 1u);       // full: tx-count arrival
            MBAR_INIT(sb + OFF_BAR + s * 16 + 8, 8u);   // empty: 8 consumer warps
        }
        asm volatile("fence.proxy.async.shared::cta;" ::: "memory");
    }
    __syncthreads();

    const int grid = gridDim.x;
    const int bid = blockIdx.x;

    // =================== producer warp (warp 8) ===================
    if (wid == 8) {
        if (lid == 0) {
            uint32_t g = 0;   // global stage counter for this CTA's stream
            for (int t = bid; t < NTILES; t += grid) {
                int m0, n0;
                tile_mn(t, m0, n0);
                const char* a_tiles = (const char*)g_A + ((size_t)(m0 / TM) * 64) * A_SUB;
                const char* w_tiles = (const char*)g_W + ((size_t)(n0 / TN) * 64) * W_SUB;
                for (int it = 0; it < SITERS; ++it, ++g) {
                    uint32_t s = g & (STAGES - 1);
                    uint32_t fb = sb + OFF_BAR + s * 16;
                    mbar_wait_relaxed(fb + 8, ((g >> 1) & 1u) ^ 1u);
                    MBAR_EXPECT_TX(fb, (uint32_t)STAGE_BYTES);
                    uint32_t stg = sb + s * STAGE_BYTES;
                    bulk_g2s(stg,         a_tiles + (size_t)it * A_STG, A_STG, fb);
                    bulk_g2s(stg + A_STG, w_tiles + (size_t)it * W_STG, W_STG, fb);
                }
            }
        }
        return;
    }

    // =================== consumer warps (0..7), warp tile 64x64 ===================
    const int warp_m = wid & 1;      // 2 along M, 64 rows each
    const int warp_n = wid >> 1;     // 4 along N, 64 cols each

    int lrow = lid & 15;
    int lk16 = (lid >> 4) * 16;
    uint32_t a_rb[4], a_rx[4];
    #pragma unroll
    for (int mtt = 0; mtt < 4; ++mtt) {
        int rowi = warp_m * 64 + mtt * 16 + lrow;
        a_rb[mtt] = rowi * 128;
        a_rx[mtt] = (rowi & 7) << 4;
    }
    uint32_t b_rb[4], b_rx[4];
    #pragma unroll
    for (int nb = 0; nb < 4; ++nb) {
        int rowi = warp_n * 64 + nb * 16 + lrow;
        b_rb[nb] = A_STG + rowi * 128;   // W sub-tile 0 base within stage
        b_rx[nb] = (rowi & 7) << 4;
    }

    const int qrow = lid >> 2;
    const int qcol = (lid & 3) * 2;

    uint32_t g = 0;
    for (int t = bid; t < NTILES; t += grid) {
        int m0, n0;
        tile_mn(t, m0, n0);

        float acc[4][8][4];
        #pragma unroll
        for (int i = 0; i < 4; ++i)
            #pragma unroll
            for (int j = 0; j < 8; ++j)
                #pragma unroll
                for (int k = 0; k < 4; ++k) acc[i][j][k] = 0.0f;

        for (int it = 0; it < SITERS; ++it, ++g) {
            uint32_t s = g & (STAGES - 1);
            mbar_wait(sb + OFF_BAR + s * 16, (g >> 1) & 1u);

            uint32_t st = sb + s * STAGE_BYTES;

            // fragment buffers reborn each iteration (no loop-carry -> no spill)
            uint32_t a[2][4][4], b[2][4][4];
            {   // prime ks0 (sub-tile 0, kb = lk16)
                uint32_t kb = lk16;
                #pragma unroll
                for (int mtt = 0; mtt < 4; ++mtt)
                    ldsm4(a[0][mtt], st + a_rb[mtt] + (kb ^ a_rx[mtt]));
                #pragma unroll
                for (int nb = 0; nb < 4; ++nb)
                    ldsm4(b[0][nb], st + b_rb[nb] + (kb ^ b_rx[nb]));
            }

            #pragma unroll
            for (int ks = 0; ks < 8; ++ks) {
                const int cur = ks & 1;
                const int nxt = cur ^ 1;
                if (ks < 7) {
                    // prefetch ks+1 fragments (sub-tile (ks+1)>>2, kb = ((ks+1)&3)*32)
                    const int ksn = ks + 1;
                    uint32_t asub = (ksn & 4) ? (uint32_t)A_SUB : 0u;
                    uint32_t wsub = (ksn & 4) ? (uint32_t)W_SUB : 0u;
                    uint32_t kb = (ksn & 3) * 32 + lk16;
                    #pragma unroll
                    for (int mtt = 0; mtt < 4; ++mtt)
                        ldsm4(a[nxt][mtt], st + asub + a_rb[mtt] + (kb ^ a_rx[mtt]));
                    #pragma unroll
                    for (int nb = 0; nb < 4; ++nb)
                        ldsm4(b[nxt][nb], st + wsub + b_rb[nb] + (kb ^ b_rx[nb]));
                    // ks==6's prefetch is the LAST smem read of this stage
                    if (ks == 6 && lid == 0) MBAR_ARRIVE(sb + OFF_BAR + s * 16 + 8);
                }
                #pragma unroll
                for (int mtt = 0; mtt < 4; ++mtt) {
                    #pragma unroll
                    for (int nb = 0; nb < 4; ++nb) {
                        mma16816(acc[mtt][2 * nb],     a[cur][mtt], b[cur][nb][0], b[cur][nb][2]);
                        mma16816(acc[mtt][2 * nb + 1], a[cur][mtt], b[cur][nb][1], b[cur][nb][3]);
                    }
                }
            }
        }

        // epilogue: scale * acc + bias, evict-first stores
        #pragma unroll
        for (int nb8 = 0; nb8 < 8; ++nb8) {
            int nl = warp_n * 64 + nb8 * 8 + qcol;
            float2 sv = __ldg(reinterpret_cast<const float2*>(scale + n0 + nl));
            float2 bv = __ldg(reinterpret_cast<const float2*>(bias + n0 + nl));
            #pragma unroll
            for (int mtt = 0; mtt < 4; ++mtt) {
                int r0 = m0 + warp_m * 64 + mtt * 16 + qrow;
                float* p0 = out + (size_t)r0 * N_TOTAL + n0 + nl;
                float* p1 = out + (size_t)(r0 + 8) * N_TOTAL + n0 + nl;
                st_cs_f32x2(p0, acc[mtt][nb8][0] * sv.x + bv.x,
                                acc[mtt][nb8][1] * sv.y + bv.y);
                st_cs_f32x2(p1, acc[mtt][nb8][2] * sv.x + bv.x,
                                acc[mtt][nb8][3] * sv.y + bv.y);
            }
        }
    }
}

// ====================== host launch ======================
extern "C" void kernel_launch(void* const* d_in, const int* in_sizes, int n_in,
                              void* d_out, int out_size) {
    const float* inp = (const float*)d_in[0];   // [4,2048,4096] fp32
    const int*   qw  = (const int*)d_in[1];     // [16384,4096] int32
    const float* sw  = (const float*)d_in[2];   // [16384]
    const float* bs  = (const float*)d_in[3];   // [16384]
    float* out = (float*)d_out;

    void *pA = nullptr, *pW = nullptr;
    cudaGetSymbolAddress(&pA, g_A);
    cudaGetSymbolAddress(&pW, g_W);

    conv_both<<<(ALL_CHUNKS + 511) / 512, 512>>>((const float4*)inp, (const int4*)qw,
                                                 (char*)pA, (char*)pW);

    static int nsm = 0;
    if (nsm == 0) {
        cudaDeviceGetAttribute(&nsm, cudaDevAttrMultiProcessorCount, 0);
        if (nsm <= 0) nsm = 148;
    }

    cudaFuncSetAttribute(qlinear_gemm, cudaFuncAttributeMaxDynamicSharedMemorySize, SMEM_DYN);
    qlinear_gemm<<<nsm, THREADS, SMEM_DYN>>>(sw, bs, out);
}

// round 16
// speedup vs baseline: 1.3275x; 1.3275x over previous
#include <cuda_runtime.h>
#include <cuda_fp16.h>
#include <cstdint>

// ====================== problem constants ======================
#define M_TOTAL 8192
#define N_TOTAL 16384
#define K_TOTAL 4096

#define TM 128
#define TN 256
#define TKS 128                  // fp16 elems of K per pipeline stage (2 x 64 sub-tiles)
#define STAGES 2
#define SITERS (K_TOTAL / TKS)   // 32 stage-iterations per tile
#define NTILES ((M_TOTAL / TM) * (N_TOTAL / TN))   // 4096
#define THREADS 544              // 16 consumer warps (4Mx4N of 32x64) + 1 producer warp

// sub-tile sizes (64-k granularity, matching the pre-tiled layout)
#define A_SUB   (TM * 64 * 2)            // 16384
#define W_SUB   (TN * 64 * 2)            // 32768
#define A_STG   (2 * A_SUB)              // 32768
#define W_STG   (2 * W_SUB)              // 65536
#define STAGE_BYTES (A_STG + W_STG)      // 98304

#define OFF_BAR   (STAGES * STAGE_BYTES)   // 196608: [full(8B), empty(8B)] x STAGES
#define SMEM_NEED (OFF_BAR + STAGES * 16)
#define SMEM_DYN  (SMEM_NEED + 1024)

// ====================== device scratch (pre-swizzled tiled layouts) ==================
// A: sub-tiles [mt][k64], 128 rows x 128B (SW128-swizzled), 16KB each, contiguous along k64
// W: sub-tiles [nt][k64], 256 rows x 128B (SW128-swizzled), 32KB each, contiguous along k64
__device__ __align__(128) __half g_A[(size_t)M_TOTAL * K_TOTAL];
__device__ __align__(128) __half g_W[(size_t)N_TOTAL * K_TOTAL];

// ====================== PTX helpers (generic PTX only) ======================
__device__ __forceinline__ uint32_t smem_u32(const void* p) {
    uint32_t a;
    asm("{ .reg .u64 t; cvta.to.shared.u64 t, %1; cvt.u32.u64 %0, t; }" : "=r"(a) : "l"(p));
    return a;
}

#define MBAR_INIT(addr, cnt) \
    asm volatile("mbarrier.init.shared.b64 [%0], %1;" :: "r"(addr), "r"(cnt) : "memory")

#define MBAR_EXPECT_TX(addr, bytes) \
    asm volatile("mbarrier.arrive.expect_tx.shared.b64 _, [%0], %1;" :: "r"(addr), "r"(bytes) : "memory")

#define MBAR_ARRIVE(addr) \
    asm volatile("mbarrier.arrive.shared.b64 _, [%0];" :: "r"(addr) : "memory")

__device__ __forceinline__ void mbar_wait(uint32_t mbar, uint32_t parity) {
    asm volatile(
        "{\n\t.reg .pred P;\n\t"
        "WAIT_%=:\n\t"
        "mbarrier.try_wait.parity.acquire.cta.shared::cta.b64 P, [%0], %1, 0x989680;\n\t"
        "@P bra.uni DONE_%=;\n\t"
        "bra.uni WAIT_%=;\n\t"
        "DONE_%=:\n\t}"
        :: "r"(mbar), "r"(parity) : "memory");
}

__device__ __forceinline__ void mbar_wait_relaxed(uint32_t mbar, uint32_t parity) {
    asm volatile(
        "{\n\t.reg .pred P;\n\t"
        "WAIT_%=:\n\t"
        "mbarrier.try_wait.parity.relaxed.cta.shared::cta.b64 P, [%0], %1, 0x989680;\n\t"
        "@P bra.uni DONE_%=;\n\t"
        "bra.uni WAIT_%=;\n\t"
        "DONE_%=:\n\t}"
        :: "r"(mbar), "r"(parity) : "memory");
}

__device__ __forceinline__ void bulk_g2s(uint32_t dst, const void* src, uint32_t bytes, uint32_t mbar) {
    asm volatile(
        "cp.async.bulk.shared::cluster.global.mbarrier::complete_tx::bytes [%0], [%1], %2, [%3];"
        :: "r"(dst), "l"(src), "r"(bytes), "r"(mbar) : "memory");
}

__device__ __forceinline__ void ldsm4(uint32_t* r, uint32_t addr) {
    asm volatile("ldmatrix.sync.aligned.m8n8.x4.shared.b16 {%0,%1,%2,%3}, [%4];"
                 : "=r"(r[0]), "=r"(r[1]), "=r"(r[2]), "=r"(r[3]) : "r"(addr));
}

__device__ __forceinline__ void mma16816(float* c, const uint32_t* a, uint32_t b0, uint32_t b1) {
    asm volatile(
        "mma.sync.aligned.m16n8k16.row.col.f32.f16.f16.f32 "
        "{%0,%1,%2,%3}, {%4,%5,%6,%7}, {%8,%9}, {%0,%1,%2,%3};"
        : "+f"(c[0]), "+f"(c[1]), "+f"(c[2]), "+f"(c[3])
        : "r"(a[0]), "r"(a[1]), "r"(a[2]), "r"(a[3]), "r"(b0), "r"(b1));
}

// evict-first fp32x2 store: keep 512MB output stream from thrashing W tiles in L2
__device__ __forceinline__ void st_cs_f32x2(float* p, float x, float y) {
    asm volatile("st.global.cs.v2.f32 [%0], {%1, %2};" :: "l"(p), "f"(x), "f"(y) : "memory");
}

// streaming 16B load / store for the conv pass (data touched exactly once)
__device__ __forceinline__ uint4 ld_cs_u4(const void* p) {
    uint4 v;
    asm volatile("ld.global.cs.v4.u32 {%0,%1,%2,%3}, [%4];"
                 : "=r"(v.x), "=r"(v.y), "=r"(v.z), "=r"(v.w) : "l"(p));
    return v;
}
__device__ __forceinline__ void st_cs_u4(void* p, uint4 v) {
    asm volatile("st.global.cs.v4.u32 [%0], {%1,%2,%3,%4};"
                 :: "l"(p), "r"(v.x), "r"(v.y), "r"(v.z), "r"(v.w) : "memory");
}

// ====================== merged pre-convert kernel (swizzled tiled layout) ======
#define A_CHUNKS ((M_TOTAL * K_TOTAL) / 8)   // 4194304
#define W_CHUNKS ((N_TOTAL * K_TOTAL) / 8)   // 8388608
#define ALL_CHUNKS (A_CHUNKS + W_CHUNKS)     // 12582912

__global__ void conv_both(const float4* __restrict__ inA, const int4* __restrict__ inW,
                          char* __restrict__ outA, char* __restrict__ outW) {
    int t = blockIdx.x * blockDim.x + threadIdx.x;
    if (t < A_CHUNKS) {
        int c  = t & 7;
        int r  = (t >> 3) & 127;
        int it = (t >> 10) & 63;
        int mt = t >> 16;
        int m = mt * 128 + r;
        int k = it * 64 + c * 8;
        const float4* src = inA + ((size_t)m * K_TOTAL + k) / 4;
        uint4 u0 = ld_cs_u4(src);
        uint4 u1 = ld_cs_u4(src + 1);
        float4 v0 = *reinterpret_cast<float4*>(&u0);
        float4 v1 = *reinterpret_cast<float4*>(&u1);
        __half2 h0 = __floats2half2_rn(v0.x, v0.y);
        __half2 h1 = __floats2half2_rn(v0.z, v0.w);
        __half2 h2 = __floats2half2_rn(v1.x, v1.y);
        __half2 h3 = __floats2half2_rn(v1.z, v1.w);
        size_t off = (size_t)(mt * 64 + it) * A_SUB + r * 128 + ((c * 16) ^ ((r & 7) << 4));
        uint4 pk;
        pk.x = *(uint32_t*)&h0; pk.y = *(uint32_t*)&h1;
        pk.z = *(uint32_t*)&h2; pk.w = *(uint32_t*)&h3;
        st_cs_u4(outA + off, pk);
    } else {
        t -= A_CHUNKS;
        if (t >= W_CHUNKS) return;
        int c  = t & 7;
        int r  = (t >> 3) & 255;
        int it = (t >> 11) & 63;
        int nt = t >> 17;
        int n = nt * 256 + r;
        int k = it * 64 + c * 8;
        const int4* src = inW + ((size_t)n * K_TOTAL + k) / 4;
        uint4 u0 = ld_cs_u4(src);
        uint4 u1 = ld_cs_u4(src + 1);
        int4 w0 = *reinterpret_cast<int4*>(&u0);
        int4 w1 = *reinterpret_cast<int4*>(&u1);
        __half2 h0 = __floats2half2_rn((float)w0.x, (float)w0.y);  // exact: |w|<=127
        __half2 h1 = __floats2half2_rn((float)w0.z, (float)w0.w);
        __half2 h2 = __floats2half2_rn((float)w1.x, (float)w1.y);
        __half2 h3 = __floats2half2_rn((float)w1.z, (float)w1.w);
        size_t off = (size_t)(nt * 64 + it) * W_SUB + r * 128 + ((c * 16) ^ ((r & 7) << 4));
        uint4 pk;
        pk.x = *(uint32_t*)&h0; pk.y = *(uint32_t*)&h1;
        pk.z = *(uint32_t*)&h2; pk.w = *(uint32_t*)&h3;
        st_cs_u4(outW + off, pk);
    }
}

// ====================== tile mapping ============
__device__ __forceinline__ void tile_mn(int t, int& m0, int& n0) {
    const int G = 8;
    const int MT = M_TOTAL / TM;          // 64
    const int PER = G * MT;               // 512
    int grp = t / PER;
    int r = t % PER;
    int nt = grp * G + (r % G);
    int mt = r / G;
    m0 = mt * TM;
    n0 = nt * TN;
}

// ====================== persistent warp-specialized GEMM (R12/R14 optimum) =====
__global__ void __launch_bounds__(THREADS, 1) qlinear_gemm(
    const float* __restrict__ scale,
    const float* __restrict__ bias,
    float* __restrict__ out)
{
    extern __shared__ char smem_raw[];
    uint32_t raw = smem_u32(smem_raw);
    uint32_t pad = (1024u - (raw & 1023u)) & 1023u;
    uint32_t sb = raw + pad;

    const int tid = threadIdx.x;
    const int wid = tid >> 5;
    const int lid = tid & 31;

    if (tid == 0) {
        #pragma unroll
        for (int s = 0; s < STAGES; ++s) {
            MBAR_INIT(sb + OFF_BAR + s * 16, 1u);        // full: tx-count arrival
            MBAR_INIT(sb + OFF_BAR + s * 16 + 8, 16u);   // empty: 16 consumer warps
        }
        asm volatile("fence.proxy.async.shared::cta;" ::: "memory");
    }
    __syncthreads();

    const int grid = gridDim.x;
    const int bid = blockIdx.x;

    // =================== producer warp (warp 16) ===================
    if (wid == 16) {
        if (lid == 0) {
            uint32_t g = 0;   // global stage counter for this CTA's stream
            for (int t = bid; t < NTILES; t += grid) {
                int m0, n0;
                tile_mn(t, m0, n0);
                const char* a_tiles = (const char*)g_A + ((size_t)(m0 / TM) * 64) * A_SUB;
                const char* w_tiles = (const char*)g_W + ((size_t)(n0 / TN) * 64) * W_SUB;
                for (int it = 0; it < SITERS; ++it, ++g) {
                    uint32_t s = g & (STAGES - 1);
                    uint32_t fb = sb + OFF_BAR + s * 16;
                    mbar_wait_relaxed(fb + 8, ((g >> 1) & 1u) ^ 1u);
                    MBAR_EXPECT_TX(fb, (uint32_t)STAGE_BYTES);
                    uint32_t stg = sb + s * STAGE_BYTES;
                    bulk_g2s(stg,         a_tiles + (size_t)it * A_STG, A_STG, fb);
                    bulk_g2s(stg + A_STG, w_tiles + (size_t)it * W_STG, W_STG, fb);
                }
            }
        }
        return;
    }

    // =================== consumer warps (0..15), warp tile 32x64 ===================
    const int warp_m = wid & 3;      // 4 along M, 32 rows each
    const int warp_n = wid >> 2;     // 4 along N, 64 cols each

    int lrow = lid & 15;
    int lk16 = (lid >> 4) * 16;
    uint32_t a_rb[2], a_rx[2];
    #pragma unroll
    for (int mtt = 0; mtt < 2; ++mtt) {
        int rowi = warp_m * 32 + mtt * 16 + lrow;
        a_rb[mtt] = rowi * 128;
        a_rx[mtt] = (rowi & 7) << 4;
    }
    uint32_t b_rb[4], b_rx[4];
    #pragma unroll
    for (int nb = 0; nb < 4; ++nb) {
        int rowi = warp_n * 64 + nb * 16 + lrow;
        b_rb[nb] = A_STG + rowi * 128;   // W sub-tile 0 base within stage
        b_rx[nb] = (rowi & 7) << 4;
    }

    const int qrow = lid >> 2;
    const int qcol = (lid & 3) * 2;

    uint32_t g = 0;
    for (int t = bid; t < NTILES; t += grid) {
        int m0, n0;
        tile_mn(t, m0, n0);

        float acc[2][8][4];
        #pragma unroll
        for (int i = 0; i < 2; ++i)
            #pragma unroll
            for (int j = 0; j < 8; ++j)
                #pragma unroll
                for (int k = 0; k < 4; ++k) acc[i][j][k] = 0.0f;

        for (int it = 0; it < SITERS; ++it, ++g) {
            uint32_t s = g & (STAGES - 1);
            mbar_wait(sb + OFF_BAR + s * 16, (g >> 1) & 1u);

            uint32_t st = sb + s * STAGE_BYTES;

            // fragment buffers reborn each iteration (no loop-carry -> no spill)
            uint32_t a[2][2][4], b[2][4][4];
            {   // prime ks0 (sub-tile 0, kb = lk16)
                uint32_t kb = lk16;
                #pragma unroll
                for (int mtt = 0; mtt < 2; ++mtt)
                    ldsm4(a[0][mtt], st + a_rb[mtt] + (kb ^ a_rx[mtt]));
                #pragma unroll
                for (int nb = 0; nb < 4; ++nb)
                    ldsm4(b[0][nb], st + b_rb[nb] + (kb ^ b_rx[nb]));
            }

            #pragma unroll
            for (int ks = 0; ks < 8; ++ks) {
                const int cur = ks & 1;
                const int nxt = cur ^ 1;
                if (ks < 7) {
                    // prefetch ks+1 fragments (sub-tile (ks+1)>>2, kb = ((ks+1)&3)*32)
                    const int ksn = ks + 1;
                    uint32_t asub = (ksn & 4) ? (uint32_t)A_SUB : 0u;
                    uint32_t wsub = (ksn & 4) ? (uint32_t)W_SUB : 0u;
                    uint32_t kb = (ksn & 3) * 32 + lk16;
                    #pragma unroll
                    for (int mtt = 0; mtt < 2; ++mtt)
                        ldsm4(a[nxt][mtt], st + asub + a_rb[mtt] + (kb ^ a_rx[mtt]));
                    #pragma unroll
                    for (int nb = 0; nb < 4; ++nb)
                        ldsm4(b[nxt][nb], st + wsub + b_rb[nb] + (kb ^ b_rx[nb]));
                    // ks==6's prefetch is the LAST smem read of this stage
                    if (ks == 6 && lid == 0) MBAR_ARRIVE(sb + OFF_BAR + s * 16 + 8);
                }
                #pragma unroll
                for (int mtt = 0; mtt < 2; ++mtt) {
                    #pragma unroll
                    for (int nb = 0; nb < 4; ++nb) {
                        mma16816(acc[mtt][2 * nb],     a[cur][mtt], b[cur][nb][0], b[cur][nb][2]);
                        mma16816(acc[mtt][2 * nb + 1], a[cur][mtt], b[cur][nb][1], b[cur][nb][3]);
                    }
                }
            }
        }

        // epilogue: scale * acc + bias, evict-first stores
        #pragma unroll
        for (int nb8 = 0; nb8 < 8; ++nb8) {
            int nl = warp_n * 64 + nb8 * 8 + qcol;
            float2 sv = __ldg(reinterpret_cast<const float2*>(scale + n0 + nl));
            float2 bv = __ldg(reinterpret_cast<const float2*>(bias + n0 + nl));
            #pragma unroll
            for (int mtt = 0; mtt < 2; ++mtt) {
                int r0 = m0 + warp_m * 32 + mtt * 16 + qrow;
                float* p0 = out + (size_t)r0 * N_TOTAL + n0 + nl;
                float* p1 = out + (size_t)(r0 + 8) * N_TOTAL + n0 + nl;
                st_cs_f32x2(p0, acc[mtt][nb8][0] * sv.x + bv.x,
                                acc[mtt][nb8][1] * sv.y + bv.y);
                st_cs_f32x2(p1, acc[mtt][nb8][2] * sv.x + bv.x,
                                acc[mtt][nb8][3] * sv.y + bv.y);
            }
        }
    }
}

// ====================== host launch ======================
extern "C" void kernel_launch(void* const* d_in, const int* in_sizes, int n_in,
                              void* d_out, int out_size) {
    const float* inp = (const float*)d_in[0];   // [4,2048,4096] fp32
    const int*   qw  = (const int*)d_in[1];     // [16384,4096] int32
    const float* sw  = (const float*)d_in[2];   // [16384]
    const float* bs  = (const float*)d_in[3];   // [16384]
    float* out = (float*)d_out;

    void *pA = nullptr, *pW = nullptr;
    cudaGetSymbolAddress(&pA, g_A);
    cudaGetSymbolAddress(&pW, g_W);

    conv_both<<<(ALL_CHUNKS + 511) / 512, 512>>>((const float4*)inp, (const int4*)qw,
                                                 (char*)pA, (char*)pW);

    static int nsm = 0;
    if (nsm == 0) {
        cudaDeviceGetAttribute(&nsm, cudaDevAttrMultiProcessorCount, 0);
        if (nsm <= 0) nsm = 148;
    }

    cudaFuncSetAttribute(qlinear_gemm, cudaFuncAttributeMaxDynamicSharedMemorySize, SMEM_DYN);
    qlinear_gemm<<<nsm, THREADS, SMEM_DYN>>>(sw, bs, out);
}

// round 17
// speedup vs baseline: 1.3306x; 1.0023x over previous
#include <cuda_runtime.h>
#include <cuda_fp16.h>
#include <cstdint>

// ====================== problem constants ======================
#define M_TOTAL 8192
#define N_TOTAL 16384
#define K_TOTAL 4096

#define TM 128
#define TN 256
#define TKS 128                  // fp16 elems of K per pipeline stage (2 x 64 sub-tiles)
#define STAGES 2
#define SITERS (K_TOTAL / TKS)   // 32 stage-iterations per tile
#define NTILES ((M_TOTAL / TM) * (N_TOTAL / TN))   // 4096
#define THREADS 544              // 16 consumer warps (4Mx4N of 32x64) + 1 producer warp

// sub-tile sizes (64-k granularity, matching the pre-tiled layout)
#define A_SUB   (TM * 64 * 2)            // 16384
#define W_SUB   (TN * 64 * 2)            // 32768
#define A_STG   (2 * A_SUB)              // 32768
#define W_STG   (2 * W_SUB)              // 65536
#define STAGE_BYTES (A_STG + W_STG)      // 98304

#define OFF_BAR   (STAGES * STAGE_BYTES)   // 196608: [full(8B), empty(8B)] x STAGES
#define SMEM_NEED (OFF_BAR + STAGES * 16)
#define SMEM_DYN  (SMEM_NEED + 1024)

// ====================== device scratch (pre-swizzled tiled layouts) ==================
// A: sub-tiles [mt][k64], 128 rows x 128B (SW128-swizzled), 16KB each, contiguous along k64
// W: sub-tiles [nt][k64], 256 rows x 128B (SW128-swizzled), 32KB each, contiguous along k64
__device__ __align__(128) __half g_A[(size_t)M_TOTAL * K_TOTAL];
__device__ __align__(128) __half g_W[(size_t)N_TOTAL * K_TOTAL];

// ====================== PTX helpers (generic PTX only) ======================
__device__ __forceinline__ uint32_t smem_u32(const void* p) {
    uint32_t a;
    asm("{ .reg .u64 t; cvta.to.shared.u64 t, %1; cvt.u32.u64 %0, t; }" : "=r"(a) : "l"(p));
    return a;
}

#define MBAR_INIT(addr, cnt) \
    asm volatile("mbarrier.init.shared.b64 [%0], %1;" :: "r"(addr), "r"(cnt) : "memory")

#define MBAR_EXPECT_TX(addr, bytes) \
    asm volatile("mbarrier.arrive.expect_tx.shared.b64 _, [%0], %1;" :: "r"(addr), "r"(bytes) : "memory")

#define MBAR_ARRIVE(addr) \
    asm volatile("mbarrier.arrive.shared.b64 _, [%0];" :: "r"(addr) : "memory")

__device__ __forceinline__ void mbar_wait(uint32_t mbar, uint32_t parity) {
    asm volatile(
        "{\n\t.reg .pred P;\n\t"
        "WAIT_%=:\n\t"
        "mbarrier.try_wait.parity.acquire.cta.shared::cta.b64 P, [%0], %1, 0x989680;\n\t"
        "@P bra.uni DONE_%=;\n\t"
        "bra.uni WAIT_%=;\n\t"
        "DONE_%=:\n\t}"
        :: "r"(mbar), "r"(parity) : "memory");
}

__device__ __forceinline__ void mbar_wait_relaxed(uint32_t mbar, uint32_t parity) {
    asm volatile(
        "{\n\t.reg .pred P;\n\t"
        "WAIT_%=:\n\t"
        "mbarrier.try_wait.parity.relaxed.cta.shared::cta.b64 P, [%0], %1, 0x989680;\n\t"
        "@P bra.uni DONE_%=;\n\t"
        "bra.uni WAIT_%=;\n\t"
        "DONE_%=:\n\t}"
        :: "r"(mbar), "r"(parity) : "memory");
}

__device__ __forceinline__ void bulk_g2s(uint32_t dst, const void* src, uint32_t bytes, uint32_t mbar) {
    asm volatile(
        "cp.async.bulk.shared::cluster.global.mbarrier::complete_tx::bytes [%0], [%1], %2, [%3];"
        :: "r"(dst), "l"(src), "r"(bytes), "r"(mbar) : "memory");
}

__device__ __forceinline__ void ldsm4(uint32_t* r, uint32_t addr) {
    asm volatile("ldmatrix.sync.aligned.m8n8.x4.shared.b16 {%0,%1,%2,%3}, [%4];"
                 : "=r"(r[0]), "=r"(r[1]), "=r"(r[2]), "=r"(r[3]) : "r"(addr));
}

__device__ __forceinline__ void mma16816(float* c, const uint32_t* a, uint32_t b0, uint32_t b1) {
    asm volatile(
        "mma.sync.aligned.m16n8k16.row.col.f32.f16.f16.f32 "
        "{%0,%1,%2,%3}, {%4,%5,%6,%7}, {%8,%9}, {%0,%1,%2,%3};"
        : "+f"(c[0]), "+f"(c[1]), "+f"(c[2]), "+f"(c[3])
        : "r"(a[0]), "r"(a[1]), "r"(a[2]), "r"(a[3]), "r"(b0), "r"(b1));
}

// evict-first fp32x2 store: keep 512MB output stream from thrashing W tiles in L2
__device__ __forceinline__ void st_cs_f32x2(float* p, float x, float y) {
    asm volatile("st.global.cs.v2.f32 [%0], {%1, %2};" :: "l"(p), "f"(x), "f"(y) : "memory");
}

// streaming 16B load / store for the conv pass (data touched exactly once)
__device__ __forceinline__ uint4 ld_cs_u4(const void* p) {
    uint4 v;
    asm volatile("ld.global.cs.v4.u32 {%0,%1,%2,%3}, [%4];"
                 : "=r"(v.x), "=r"(v.y), "=r"(v.z), "=r"(v.w) : "l"(p));
    return v;
}
__device__ __forceinline__ void st_cs_u4(void* p, uint4 v) {
    asm volatile("st.global.cs.v4.u32 [%0], {%1,%2,%3,%4};"
                 :: "l"(p), "r"(v.x), "r"(v.y), "r"(v.z), "r"(v.w) : "memory");
}

// pack 8 fp32 (as two uint4) -> 8 fp16 (one uint4)
__device__ __forceinline__ uint4 pack_f32x8(uint4 u0, uint4 u1) {
    float4 v0 = *reinterpret_cast<float4*>(&u0);
    float4 v1 = *reinterpret_cast<float4*>(&u1);
    __half2 h0 = __floats2half2_rn(v0.x, v0.y);
    __half2 h1 = __floats2half2_rn(v0.z, v0.w);
    __half2 h2 = __floats2half2_rn(v1.x, v1.y);
    __half2 h3 = __floats2half2_rn(v1.z, v1.w);
    uint4 pk;
    pk.x = *(uint32_t*)&h0; pk.y = *(uint32_t*)&h1;
    pk.z = *(uint32_t*)&h2; pk.w = *(uint32_t*)&h3;
    return pk;
}

// pack 8 int32 -> 8 fp16 (exact for |w|<=127)
__device__ __forceinline__ uint4 pack_s32x8(uint4 u0, uint4 u1) {
    int4 w0 = *reinterpret_cast<int4*>(&u0);
    int4 w1 = *reinterpret_cast<int4*>(&u1);
    __half2 h0 = __floats2half2_rn((float)w0.x, (float)w0.y);
    __half2 h1 = __floats2half2_rn((float)w0.z, (float)w0.w);
    __half2 h2 = __floats2half2_rn((float)w1.x, (float)w1.y);
    __half2 h3 = __floats2half2_rn((float)w1.z, (float)w1.w);
    uint4 pk;
    pk.x = *(uint32_t*)&h0; pk.y = *(uint32_t*)&h1;
    pk.z = *(uint32_t*)&h2; pk.w = *(uint32_t*)&h3;
    return pk;
}

// ====================== merged pre-convert kernel (2 chunks/thread) ============
#define A_CHUNKS ((M_TOTAL * K_TOTAL) / 8)   // 4194304 (even)
#define W_CHUNKS ((N_TOTAL * K_TOTAL) / 8)   // 8388608
#define ALL_CHUNKS (A_CHUNKS + W_CHUNKS)     // 12582912
#define CONV_THREADS_TOTAL (ALL_CHUNKS / 2)  // 6291456

__global__ void conv_both2(const float4* __restrict__ inA, const int4* __restrict__ inW,
                           char* __restrict__ outA, char* __restrict__ outW) {
    int t2 = blockIdx.x * blockDim.x + threadIdx.x;
    if (t2 >= CONV_THREADS_TOTAL) return;
    int q = t2 * 2;                       // even chunk index; pair (q, q+1) shares a row
    if (q < A_CHUNKS) {
        int c  = q & 7;                   // even
        int r  = (q >> 3) & 127;
        int it = (q >> 10) & 63;
        int mt = q >> 16;
        int m = mt * 128 + r;
        int k = it * 64 + c * 8;
        const float4* src = inA + ((size_t)m * K_TOTAL + k) / 4;  // 64B contiguous
        uint4 u0 = ld_cs_u4(src);
        uint4 u1 = ld_cs_u4(src + 1);
        uint4 u2 = ld_cs_u4(src + 2);
        uint4 u3 = ld_cs_u4(src + 3);
        uint4 pk0 = pack_f32x8(u0, u1);
        uint4 pk1 = pack_f32x8(u2, u3);
        size_t base = (size_t)(mt * 64 + it) * A_SUB + r * 128;
        uint32_t x = (uint32_t)(r & 7) << 4;
        st_cs_u4(outA + base + ((c * 16) ^ x),        pk0);
        st_cs_u4(outA + base + (((c + 1) * 16) ^ x),  pk1);
    } else {
        q -= A_CHUNKS;
        int c  = q & 7;                   // even
        int r  = (q >> 3) & 255;
        int it = (q >> 11) & 63;
        int nt = q >> 17;
        int n = nt * 256 + r;
        int k = it * 64 + c * 8;
        const int4* src = inW + ((size_t)n * K_TOTAL + k) / 4;    // 64B contiguous
        uint4 u0 = ld_cs_u4(src);
        uint4 u1 = ld_cs_u4(src + 1);
        uint4 u2 = ld_cs_u4(src + 2);
        uint4 u3 = ld_cs_u4(src + 3);
        uint4 pk0 = pack_s32x8(u0, u1);
        uint4 pk1 = pack_s32x8(u2, u3);
        size_t base = (size_t)(nt * 64 + it) * W_SUB + r * 128;
        uint32_t x = (uint32_t)(r & 7) << 4;
        st_cs_u4(outW + base + ((c * 16) ^ x),        pk0);
        st_cs_u4(outW + base + (((c + 1) * 16) ^ x),  pk1);
    }
}

// ====================== tile mapping ============
__device__ __forceinline__ void tile_mn(int t, int& m0, int& n0) {
    const int G = 8;
    const int MT = M_TOTAL / TM;          // 64
    const int PER = G * MT;               // 512
    int grp = t / PER;
    int r = t % PER;
    int nt = grp * G + (r % G);
    int mt = r / G;
    m0 = mt * TM;
    n0 = nt * TN;
}

// ====================== persistent warp-specialized GEMM (R12/R14 optimum) =====
__global__ void __launch_bounds__(THREADS, 1) qlinear_gemm(
    const float* __restrict__ scale,
    const float* __restrict__ bias,
    float* __restrict__ out)
{
    extern __shared__ char smem_raw[];
    uint32_t raw = smem_u32(smem_raw);
    uint32_t pad = (1024u - (raw & 1023u)) & 1023u;
    uint32_t sb = raw + pad;

    const int tid = threadIdx.x;
    const int wid = tid >> 5;
    const int lid = tid & 31;

    if (tid == 0) {
        #pragma unroll
        for (int s = 0; s < STAGES; ++s) {
            MBAR_INIT(sb + OFF_BAR + s * 16, 1u);        // full: tx-count arrival
            MBAR_INIT(sb + OFF_BAR + s * 16 + 8, 16u);   // empty: 16 consumer warps
        }
        asm volatile("fence.proxy.async.shared::cta;" ::: "memory");
    }
    __syncthreads();

    const int grid = gridDim.x;
    const int bid = blockIdx.x;

    // =================== producer warp (warp 16) ===================
    if (wid == 16) {
        if (lid == 0) {
            uint32_t g = 0;   // global stage counter for this CTA's stream
            for (int t = bid; t < NTILES; t += grid) {
                int m0, n0;
                tile_mn(t, m0, n0);
                const char* a_tiles = (const char*)g_A + ((size_t)(m0 / TM) * 64) * A_SUB;
                const char* w_tiles = (const char*)g_W + ((size_t)(n0 / TN) * 64) * W_SUB;
                for (int it = 0; it < SITERS; ++it, ++g) {
                    uint32_t s = g & (STAGES - 1);
                    uint32_t fb = sb + OFF_BAR + s * 16;
                    mbar_wait_relaxed(fb + 8, ((g >> 1) & 1u) ^ 1u);
                    MBAR_EXPECT_TX(fb, (uint32_t)STAGE_BYTES);
                    uint32_t stg = sb + s * STAGE_BYTES;
                    bulk_g2s(stg,         a_tiles + (size_t)it * A_STG, A_STG, fb);
                    bulk_g2s(stg + A_STG, w_tiles + (size_t)it * W_STG, W_STG, fb);
                }
            }
        }
        return;
    }

    // =================== consumer warps (0..15), warp tile 32x64 ===================
    const int warp_m = wid & 3;      // 4 along M, 32 rows each
    const int warp_n = wid >> 2;     // 4 along N, 64 cols each

    int lrow = lid & 15;
    int lk16 = (lid >> 4) * 16;
    uint32_t a_rb[2], a_rx[2];
    #pragma unroll
    for (int mtt = 0; mtt < 2; ++mtt) {
        int rowi = warp_m * 32 + mtt * 16 + lrow;
        a_rb[mtt] = rowi * 128;
        a_rx[mtt] = (rowi & 7) << 4;
    }
    uint32_t b_rb[4], b_rx[4];
    #pragma unroll
    for (int nb = 0; nb < 4; ++nb) {
        int rowi = warp_n * 64 + nb * 16 + lrow;
        b_rb[nb] = A_STG + rowi * 128;   // W sub-tile 0 base within stage
        b_rx[nb] = (rowi & 7) << 4;
    }

    const int qrow = lid >> 2;
    const int qcol = (lid & 3) * 2;

    uint32_t g = 0;
    for (int t = bid; t < NTILES; t += grid) {
        int m0, n0;
        tile_mn(t, m0, n0);

        float acc[2][8][4];
        #pragma unroll
        for (int i = 0; i < 2; ++i)
            #pragma unroll
            for (int j = 0; j < 8; ++j)
                #pragma unroll
                for (int k = 0; k < 4; ++k) acc[i][j][k] = 0.0f;

        for (int it = 0; it < SITERS; ++it, ++g) {
            uint32_t s = g & (STAGES - 1);
            mbar_wait(sb + OFF_BAR + s * 16, (g >> 1) & 1u);

            uint32_t st = sb + s * STAGE_BYTES;

            // fragment buffers reborn each iteration (no loop-carry -> no spill)
            uint32_t a[2][2][4], b[2][4][4];
            {   // prime ks0 (sub-tile 0, kb = lk16)
                uint32_t kb = lk16;
                #pragma unroll
                for (int mtt = 0; mtt < 2; ++mtt)
                    ldsm4(a[0][mtt], st + a_rb[mtt] + (kb ^ a_rx[mtt]));
                #pragma unroll
                for (int nb = 0; nb < 4; ++nb)
                    ldsm4(b[0][nb], st + b_rb[nb] + (kb ^ b_rx[nb]));
            }

            #pragma unroll
            for (int ks = 0; ks < 8; ++ks) {
                const int cur = ks & 1;
                const int nxt = cur ^ 1;
                if (ks < 7) {
                    // prefetch ks+1 fragments (sub-tile (ks+1)>>2, kb = ((ks+1)&3)*32)
                    const int ksn = ks + 1;
                    uint32_t asub = (ksn & 4) ? (uint32_t)A_SUB : 0u;
                    uint32_t wsub = (ksn & 4) ? (uint32_t)W_SUB : 0u;
                    uint32_t kb = (ksn & 3) * 32 + lk16;
                    #pragma unroll
                    for (int mtt = 0; mtt < 2; ++mtt)
                        ldsm4(a[nxt][mtt], st + asub + a_rb[mtt] + (kb ^ a_rx[mtt]));
                    #pragma unroll
                    for (int nb = 0; nb < 4; ++nb)
                        ldsm4(b[nxt][nb], st + wsub + b_rb[nb] + (kb ^ b_rx[nb]));
                    // ks==6's prefetch is the LAST smem read of this stage
                    if (ks == 6 && lid == 0) MBAR_ARRIVE(sb + OFF_BAR + s * 16 + 8);
                }
                #pragma unroll
                for (int mtt = 0; mtt < 2; ++mtt) {
                    #pragma unroll
                    for (int nb = 0; nb < 4; ++nb) {
                        mma16816(acc[mtt][2 * nb],     a[cur][mtt], b[cur][nb][0], b[cur][nb][2]);
                        mma16816(acc[mtt][2 * nb + 1], a[cur][mtt], b[cur][nb][1], b[cur][nb][3]);
                    }
                }
            }
        }

        // epilogue: scale * acc + bias, evict-first stores
        #pragma unroll
        for (int nb8 = 0; nb8 < 8; ++nb8) {
            int nl = warp_n * 64 + nb8 * 8 + qcol;
            float2 sv = __ldg(reinterpret_cast<const float2*>(scale + n0 + nl));
            float2 bv = __ldg(reinterpret_cast<const float2*>(bias + n0 + nl));
            #pragma unroll
            for (int mtt = 0; mtt < 2; ++mtt) {
                int r0 = m0 + warp_m * 32 + mtt * 16 + qrow;
                float* p0 = out + (size_t)r0 * N_TOTAL + n0 + nl;
                float* p1 = out + (size_t)(r0 + 8) * N_TOTAL + n0 + nl;
                st_cs_f32x2(p0, acc[mtt][nb8][0] * sv.x + bv.x,
                                acc[mtt][nb8][1] * sv.y + bv.y);
                st_cs_f32x2(p1, acc[mtt][nb8][2] * sv.x + bv.x,
                                acc[mtt][nb8][3] * sv.y + bv.y);
            }
        }
    }
}

// ====================== host launch ======================
extern "C" void kernel_launch(void* const* d_in, const int* in_sizes, int n_in,
                              void* d_out, int out_size) {
    const float* inp = (const float*)d_in[0];   // [4,2048,4096] fp32
    const int*   qw  = (const int*)d_in[1];     // [16384,4096] int32
    const float* sw  = (const float*)d_in[2];   // [16384]
    const float* bs  = (const float*)d_in[3];   // [16384]
    float* out = (float*)d_out;

    void *pA = nullptr, *pW = nullptr;
    cudaGetSymbolAddress(&pA, g_A);
    cudaGetSymbolAddress(&pW, g_W);

    conv_both2<<<(CONV_THREADS_TOTAL + 511) / 512, 512>>>(
        (const float4*)inp, (const int4*)qw, (char*)pA, (char*)pW);

    static int nsm = 0;
    if (nsm == 0) {
        cudaDeviceGetAttribute(&nsm, cudaDevAttrMultiProcessorCount, 0);
        if (nsm <= 0) nsm = 148;
    }

    cudaFuncSetAttribute(qlinear_gemm, cudaFuncAttributeMaxDynamicSharedMemorySize, SMEM_DYN);
    qlinear_gemm<<<nsm, THREADS, SMEM_DYN>>>(sw, bs, out);
}